// round 14
// baseline (speedup 1.0000x reference)
#include <cuda_runtime.h>
#include <math.h>

// Problem constants (fixed by the reference)
#define N_BAGS   64
#define GRID_W   96
#define NQ       512
#define NMEM     131072
#define DIM      256

#define NTHR     1024
#define NBLK     (NMEM / NTHR)                 // 128 CTAs, 1 row/thread
#define NTASK    (NQ * 8)                      // 4096 (cell -> qi) inserts

#define HBITS    13
#define HSIZE    (1 << HBITS)                  // 8192 slots, load factor 50%
#define HMASK    (HSIZE - 1)
#define MAXM     8                             // max matching queries per row

__device__ __forceinline__ unsigned cell_hash(int cell) {
    return ((unsigned)cell * 2654435761u) >> (32 - HBITS);
}

// ---------------------------------------------------------------------------
// Barrier-free design: every CTA builds its OWN query hash table in shared
// memory (inserts are tiny and redundant across CTAs), separated from use by
// a block-local __syncthreads only. Each CTA then scans its 1024 memory rows
// probing SMEM (29cy) and processes the rare hits warp-cooperatively.
// No grid barrier, no device-global scratch, one kernel + 2KB out-memset.
// ---------------------------------------------------------------------------
__global__ void __launch_bounds__(NTHR, 1)
fused_kernel(const float* __restrict__ q,
             const float* __restrict__ memory,
             const int*   __restrict__ bag_idx,
             const int*   __restrict__ xc,
             const int*   __restrict__ yc,
             const int*   __restrict__ bag_idxs,
             const int*   __restrict__ xs,
             const int*   __restrict__ ys,
             float*       __restrict__ out) {
    __shared__ int   s_key[HSIZE];             // cell, -1 = empty (32 KB)
    __shared__ short s_val[HSIZE];             // qi              (16 KB)
    const unsigned FULL = 0xFFFFFFFFu;

    int tidb = threadIdx.x;
    int lane = tidb & 31;

    // Issue my row's coord loads FIRST (longest input-dependent chain).
    int nrow = blockIdx.x * NTHR + tidb;
    int bi = bag_idxs[nrow];
    int xi = xs[nrow];
    int yi = ys[nrow];

    // ---- init table ----
    #pragma unroll
    for (int i = tidb; i < HSIZE; i += NTHR) s_key[i] = -1;
    __syncthreads();

    // ---- build: 4096 inserts, 4 per thread (redundant per CTA) ----
    #pragma unroll
    for (int k = 0; k < NTASK / NTHR; k++) {
        int t  = tidb + k * NTHR;              // 0 .. 4095
        int qi = t >> 3, nb = t & 7;
        int idx = nb + (nb >= 4 ? 1 : 0);      // 0..8 skipping center (4)
        int dx = idx % 3 - 1, dy = idx / 3 - 1;
        int x = xc[qi] + dx, y = yc[qi] + dy;
        if (x >= 0 && x < GRID_W && y >= 0 && y < GRID_W) {
            int cell = (bag_idx[qi] * GRID_W + y) * GRID_W + x;
            unsigned h = cell_hash(cell);
            while (atomicCAS(&s_key[h], -1, cell) != -1)
                h = (h + 1) & HMASK;           // occupied (maybe same cell): next
            s_val[h] = (short)qi;              // safe: read only after sync
        }
    }
    __syncthreads();

    // ---- scan: my one memory row probes the SMEM table ----
    int cell = (bi * GRID_W + yi) * GRID_W + xi;
    int m = 0;
    int qm[MAXM];
    {
        unsigned h = cell_hash(cell);
        #pragma unroll 1
        for (int it = 0; it < HSIZE; it++) {
            int kk = s_key[h];
            if (kk == -1) break;
            if (kk == cell && m < MAXM) qm[m++] = (int)s_val[h];
            h = (h + 1) & HMASK;
        }
    }

    // ---- warp-cooperative processing of the rare hits ----
    for (;;) {
        unsigned ball = __ballot_sync(FULL, m > 0);
        if (!ball) break;
        int src  = __ffs(ball) - 1;
        int top  = (m > 0) ? qm[m - 1] : 0;
        int qi_b = __shfl_sync(FULL, top, src);
        int n_b  = __shfl_sync(FULL, nrow, src);

        const float* mr = memory + (size_t)n_b * DIM + lane * 8;
        float4 m0 = *(const float4*)(mr);
        float4 m1 = *(const float4*)(mr + 4);
        const float* qr = q + qi_b * DIM + lane * 8;
        float4 a = *(const float4*)(qr);
        float4 b = *(const float4*)(qr + 4);

        float d  = a.x * m0.x + a.y * m0.y + a.z * m0.z + a.w * m0.w
                 + b.x * m1.x + b.y * m1.y + b.z * m1.z + b.w * m1.w;
        float ss = a.x * a.x + a.y * a.y + a.z * a.z + a.w * a.w
                 + b.x * b.x + b.y * b.y + b.z * b.z + b.w * b.w;
        #pragma unroll
        for (int o = 16; o; o >>= 1) {         // fused dual reduction
            d  += __shfl_xor_sync(FULL, d, o);
            ss += __shfl_xor_sync(FULL, ss, o);
        }
        if (lane == src) {
            m--;
            atomicAdd(&out[qi_b], __expf(d * 5.0f * rsqrtf(ss)));
        }
    }
}

extern "C" void kernel_launch(void* const* d_in, const int* in_sizes, int n_in,
                              void* d_out, int out_size) {
    const float* q        = (const float*)d_in[0];   // [512, 256]
    const float* memory   = (const float*)d_in[1];   // [131072, 256]
    const int*   bag_idx  = (const int*)d_in[2];     // [512]
    const int*   x_coord  = (const int*)d_in[3];     // [512]
    const int*   y_coord  = (const int*)d_in[4];     // [512]
    const int*   bag_idxs = (const int*)d_in[5];     // [131072]
    const int*   x_coords = (const int*)d_in[6];     // [131072]
    const int*   y_coords = (const int*)d_in[7];     // [131072]
    float* out = (float*)d_out;                      // [512]

    // out is the atomicAdd target: zero its 2 KB (graph-capturable).
    cudaMemsetAsync(out, 0, NQ * sizeof(float));

    fused_kernel<<<NBLK, NTHR>>>(q, memory, bag_idx, x_coord, y_coord,
                                 bag_idxs, x_coords, y_coords, out);
}

// round 15
// speedup vs baseline: 1.4581x; 1.4581x over previous
#include <cuda_runtime.h>
#include <math.h>

// Problem constants (fixed by the reference)
#define N_BAGS   64
#define GRID_W   96
#define NCELLS   (N_BAGS * GRID_W * GRID_W)   // 589824
#define CAP      16        // ring slots/cell; per-launch occupancy >16 ~impossible
#define NQ       512
#define NMEM     131072
#define DIM      256

#define NBLK     128
#define NTHR     1024                          // 131072 threads == NMEM rows
#define NTASK    (NQ * 8)                      // 4096 tasks == 4096 warps exactly

// Scratch: device globals (no runtime allocation allowed). NOTHING is reset:
//  - g_cnt is a monotonic slot allocator (only & 15 of it is used; never read
//    by phase 2, never zeroed).
//  - items carry the launch tag in their high word; stale items (old tag)
//    are ignored at read time. Zero-init BSS = tag 0, and tag = epoch+1 >= 1,
//    so launch 0 is consistent too.
__device__ unsigned           g_cnt[NCELLS];
__device__ unsigned long long g_items[NCELLS * CAP];
__device__ unsigned           g_epoch;

// ---- software grid barrier (128 CTAs, all co-resident by construction) ----
__device__ unsigned          g_bar_cnt;
__device__ volatile unsigned g_bar_gen;

__device__ __forceinline__ void grid_sync() {
    __syncthreads();
    if (threadIdx.x == 0) {
        __threadfence();
        unsigned gen = g_bar_gen;
        if (atomicAdd(&g_bar_cnt, 1u) == (unsigned)(gridDim.x - 1)) {
            g_bar_cnt = 0;
            __threadfence();
            g_bar_gen = gen + 1;               // release
        } else {
            while (g_bar_gen == gen) { }       // spin (volatile load)
        }
        __threadfence();
    }
    __syncthreads();
}

// ---------------------------------------------------------------------------
// Single fused kernel, ONE graph node, ONE grid barrier, ZERO resets.
//   Pre-barrier (overlapped): row coords (first), P2 prep (task coords,
//     q row, ||q|| reduce), out[] zeroing, P1 scatter = blind atomicAdd
//     slot claim + tagged 8B item store (one L2 round trip).
//   Post-barrier: ONE coalesced 128B load of all 16 slots -> tag select ->
//     4-wide pipelined row loads -> exp -> atomicAdd.
// ---------------------------------------------------------------------------
__global__ void __launch_bounds__(NTHR, 1)
fused_kernel(const float* __restrict__ q,
             const float* __restrict__ memory,
             const int*   __restrict__ bag_idx,
             const int*   __restrict__ xc,
             const int*   __restrict__ yc,
             const int*   __restrict__ bag_idxs,
             const int*   __restrict__ xs,
             const int*   __restrict__ ys,
             float*       __restrict__ out) {
    const unsigned FULL = 0xFFFFFFFFu;
    int tid  = blockIdx.x * NTHR + threadIdx.x;          // 0 .. 131071
    int lane = threadIdx.x & 31;

    // ================= PRE-BARRIER (everything overlaps) =================

    // ---- P1 inputs first: this chain feeds the barrier ----
    int bi = bag_idxs[tid];
    int xi = xs[tid];
    int yi = ys[tid];

    unsigned tag = g_epoch + 1u;                         // uniform, >= 1

    // ---- P2 prep: one task per warp, depends only on kernel inputs ----
    int task = tid >> 5;                                 // 0 .. 4095
    int qi   = task >> 3;
    int nb   = task & 7;

    const float* qrow = q + qi * DIM + lane * 8;
    float4 a = *(const float4*)(qrow);
    float4 b = *(const float4*)(qrow + 4);

    int nidx = nb + (nb >= 4 ? 1 : 0);                   // 0..8 skip center
    int dxn = nidx % 3 - 1, dyn = nidx / 3 - 1;
    int xq = xc[qi] + dxn, yq = yc[qi] + dyn;
    bool valid = (xq >= 0) & (xq < GRID_W) & (yq >= 0) & (yq < GRID_W);
    int cell2 = (bag_idx[qi] * GRID_W + yq) * GRID_W + xq;

    // ---- P1: blind slot claim + tagged item store; zero out[] ----
    if (tid < NQ) out[tid] = 0.0f;
    {
        int cell = (bi * GRID_W + yi) * GRID_W + xi;
        unsigned slot = atomicAdd(&g_cnt[cell], 1u) & (CAP - 1u);
        g_items[cell * CAP + slot] =
            ((unsigned long long)tag << 32) | (unsigned)tid;
    }

    // ---- ||q|| reduce (no memory deps; fills latency before barrier) ----
    float ss = a.x * a.x + a.y * a.y + a.z * a.z + a.w * a.w
             + b.x * b.x + b.y * b.y + b.z * b.z + b.w * b.w;
    #pragma unroll
    for (int o = 16; o; o >>= 1) ss += __shfl_xor_sync(FULL, ss, o);
    float inv = rsqrtf(ss) * 5.0f;                       // 1 / (||q|| * 0.2)

    grid_sync();
    if (tid == 0) g_epoch = tag;                         // bump for next launch

    // ================= POST-BARRIER (short chain) =================
    if (!valid) return;                                  // warp-uniform

    // ONE coalesced 128B round trip: lanes 0..15 load the cell's 16 slots.
    unsigned long long e = (lane < CAP) ? g_items[cell2 * CAP + lane] : 0ULL;
    unsigned rowv = (unsigned)e;
    bool hit = ((unsigned)(e >> 32) == tag);

    unsigned ball = __ballot_sync(FULL, hit);            // uniform
    if (!ball) return;

    float s = 0.0f;
    while (ball) {
        // peel up to 4 hits; srcs computed identically on every lane
        int srcs[4], navail = 0;
        #pragma unroll
        for (int j = 0; j < 4; j++) {
            if (ball) { srcs[j] = __ffs(ball) - 1; ball &= ball - 1; navail++; }
            else      { srcs[j] = srcs[0]; }             // dup (cached row)
        }
        float d[4];
        #pragma unroll
        for (int j = 0; j < 4; j++) {
            int n = __shfl_sync(FULL, rowv, srcs[j]);
            const float* mr = memory + (size_t)n * DIM + lane * 8;
            float4 m0 = *(const float4*)(mr);
            float4 m1 = *(const float4*)(mr + 4);
            d[j] = a.x * m0.x + a.y * m0.y + a.z * m0.z + a.w * m0.w
                 + b.x * m1.x + b.y * m1.y + b.z * m1.z + b.w * m1.w;
        }
        #pragma unroll
        for (int o = 16; o; o >>= 1) {                   // 4 interleaved reductions
            d[0] += __shfl_xor_sync(FULL, d[0], o);
            d[1] += __shfl_xor_sync(FULL, d[1], o);
            d[2] += __shfl_xor_sync(FULL, d[2], o);
            d[3] += __shfl_xor_sync(FULL, d[3], o);
        }
        #pragma unroll
        for (int j = 0; j < 4; j++)
            if (j < navail) s += __expf(d[j] * inv);
    }
    if (lane == 0) atomicAdd(&out[qi], s);
}

extern "C" void kernel_launch(void* const* d_in, const int* in_sizes, int n_in,
                              void* d_out, int out_size) {
    const float* q        = (const float*)d_in[0];   // [512, 256]
    const float* memory   = (const float*)d_in[1];   // [131072, 256]
    const int*   bag_idx  = (const int*)d_in[2];     // [512]
    const int*   x_coord  = (const int*)d_in[3];     // [512]
    const int*   y_coord  = (const int*)d_in[4];     // [512]
    const int*   bag_idxs = (const int*)d_in[5];     // [131072]
    const int*   x_coords = (const int*)d_in[6];     // [131072]
    const int*   y_coords = (const int*)d_in[7];     // [131072]
    float* out = (float*)d_out;                      // [512]

    fused_kernel<<<NBLK, NTHR>>>(q, memory, bag_idx, x_coord, y_coord,
                                 bag_idxs, x_coords, y_coords, out);
}